// round 1
// baseline (speedup 1.0000x reference)
#include <cuda_runtime.h>
#include <math.h>

#define BSZ 16
#define SDIM 1024
#define EDIM 1024
#define HDIM 2048

// ---------------- scratch (device globals; no allocations) ----------------
__device__ float g_q[(size_t)BSZ * SDIM * EDIM];   // q, later attn output
__device__ float g_k[(size_t)BSZ * SDIM * EDIM];   // k, later ff output
__device__ float g_v[(size_t)BSZ * SDIM * EDIM];   // v
__device__ float g_w[(size_t)BSZ * SDIM * SDIM];   // scores / softmax weights
__device__ float g_x[(size_t)BSZ * SDIM * EDIM];   // post-LN1
__device__ float g_h[(size_t)BSZ * SDIM * HDIM];   // FFN hidden
__device__ float g_part[BSZ * 64];                 // softmax partials
__device__ float g_bmax[BSZ];
__device__ float g_binv[BSZ];

// ---------------- GEMM: C = alpha * A @ B (+ optional per-batch alpha) -----
// A: [M,K] row-major. B: BT ? [N,K] row-major : [K,N] row-major. C: [M,N].
// BM=BN=128, BK=16, 256 threads, 8x8 per-thread tile. Dims must be multiples
// of the tile (true for all launches here).
template <bool BT>
__global__ __launch_bounds__(256)
void gemm_kernel(const float* __restrict__ A, const float* __restrict__ Bm,
                 float* __restrict__ C,
                 int M, int N, int K,
                 long long sA, long long sB, long long sC,
                 float alpha, const float* __restrict__ alphaPtr)
{
    __shared__ float As[16][132];
    __shared__ float Bs[16][132];

    const int bz = blockIdx.z;
    A  += (long long)bz * sA;
    Bm += (long long)bz * sB;
    C  += (long long)bz * sC;

    const int tid = threadIdx.x;
    const int tx = tid & 15;
    const int ty = tid >> 4;
    const int m0 = blockIdx.y * 128;
    const int n0 = blockIdx.x * 128;

    float acc[8][8];
#pragma unroll
    for (int i = 0; i < 8; i++)
#pragma unroll
        for (int j = 0; j < 8; j++) acc[i][j] = 0.f;

    for (int kt = 0; kt < K; kt += 16) {
        // ---- load A tile (128 rows x 16 cols), store transposed ----
#pragma unroll
        for (int r = 0; r < 2; r++) {
            int f = tid * 2 + r;           // 0..511 float4 slots
            int row = f >> 2;              // 0..127
            int c4 = (f & 3) * 4;          // 0,4,8,12
            float4 v4 = *(const float4*)&A[(long long)(m0 + row) * K + kt + c4];
            As[c4 + 0][row] = v4.x;
            As[c4 + 1][row] = v4.y;
            As[c4 + 2][row] = v4.z;
            As[c4 + 3][row] = v4.w;
        }
        // ---- load B tile ----
        if (BT) {
            // B[N,K]: 128 n-rows x 16 k-cols, store transposed
#pragma unroll
            for (int r = 0; r < 2; r++) {
                int f = tid * 2 + r;
                int row = f >> 2;
                int c4 = (f & 3) * 4;
                float4 v4 = *(const float4*)&Bm[(long long)(n0 + row) * K + kt + c4];
                Bs[c4 + 0][row] = v4.x;
                Bs[c4 + 1][row] = v4.y;
                Bs[c4 + 2][row] = v4.z;
                Bs[c4 + 3][row] = v4.w;
            }
        } else {
            // B[K,N]: 16 k-rows x 128 n-cols, direct float4 store
#pragma unroll
            for (int r = 0; r < 2; r++) {
                int f = tid * 2 + r;       // 512 float4: 16 rows x 32 f4/row
                int row = f >> 5;
                int c4 = (f & 31) * 4;
                *(float4*)&Bs[row][c4] =
                    *(const float4*)&Bm[(long long)(kt + row) * N + n0 + c4];
            }
        }
        __syncthreads();

#pragma unroll
        for (int k = 0; k < 16; k++) {
            float a[8], b[8];
            *(float4*)&a[0] = *(float4*)&As[k][ty * 8];
            *(float4*)&a[4] = *(float4*)&As[k][ty * 8 + 4];
            *(float4*)&b[0] = *(float4*)&Bs[k][tx * 8];
            *(float4*)&b[4] = *(float4*)&Bs[k][tx * 8 + 4];
#pragma unroll
            for (int i = 0; i < 8; i++)
#pragma unroll
                for (int j = 0; j < 8; j++)
                    acc[i][j] = fmaf(a[i], b[j], acc[i][j]);
        }
        __syncthreads();
    }

    float al = alpha;
    if (alphaPtr) al *= alphaPtr[bz];

#pragma unroll
    for (int i = 0; i < 8; i++) {
        long long row = m0 + ty * 8 + i;
        float4 o0, o1;
        o0.x = acc[i][0] * al; o0.y = acc[i][1] * al;
        o0.z = acc[i][2] * al; o0.w = acc[i][3] * al;
        o1.x = acc[i][4] * al; o1.y = acc[i][5] * al;
        o1.z = acc[i][6] * al; o1.w = acc[i][7] * al;
        *(float4*)&C[row * N + n0 + tx * 8]     = o0;
        *(float4*)&C[row * N + n0 + tx * 8 + 4] = o1;
    }
}

// ---------------- softmax over flattened S*S per batch ----------------
__global__ __launch_bounds__(256)
void max_part_kernel(const float* __restrict__ w, float* __restrict__ part)
{
    const int b = blockIdx.y;
    const float4* p = (const float4*)(w + (size_t)b * SDIM * SDIM)
                      + (size_t)blockIdx.x * 4096;
    float m = -3.4e38f;
    for (int i = threadIdx.x; i < 4096; i += 256) {
        float4 v = p[i];
        m = fmaxf(m, fmaxf(fmaxf(v.x, v.y), fmaxf(v.z, v.w)));
    }
    __shared__ float sh[256];
    sh[threadIdx.x] = m;
    __syncthreads();
    for (int o = 128; o > 0; o >>= 1) {
        if (threadIdx.x < o)
            sh[threadIdx.x] = fmaxf(sh[threadIdx.x], sh[threadIdx.x + o]);
        __syncthreads();
    }
    if (threadIdx.x == 0) part[b * 64 + blockIdx.x] = sh[0];
}

__global__ void fin_max_kernel(const float* __restrict__ part, float* __restrict__ bmax)
{
    const int b = blockIdx.x;
    __shared__ float sh[64];
    sh[threadIdx.x] = part[b * 64 + threadIdx.x];
    __syncthreads();
    for (int o = 32; o > 0; o >>= 1) {
        if (threadIdx.x < o)
            sh[threadIdx.x] = fmaxf(sh[threadIdx.x], sh[threadIdx.x + o]);
        __syncthreads();
    }
    if (threadIdx.x == 0) bmax[b] = sh[0];
}

__global__ __launch_bounds__(256)
void expsum_kernel(float* __restrict__ w, const float* __restrict__ bmax,
                   float* __restrict__ part)
{
    const int b = blockIdx.y;
    const float m = bmax[b];
    float4* p = (float4*)(w + (size_t)b * SDIM * SDIM) + (size_t)blockIdx.x * 4096;
    float s = 0.f;
    for (int i = threadIdx.x; i < 4096; i += 256) {
        float4 v = p[i];
        v.x = __expf(v.x - m);
        v.y = __expf(v.y - m);
        v.z = __expf(v.z - m);
        v.w = __expf(v.w - m);
        s += (v.x + v.y) + (v.z + v.w);
        p[i] = v;
    }
    __shared__ float sh[256];
    sh[threadIdx.x] = s;
    __syncthreads();
    for (int o = 128; o > 0; o >>= 1) {
        if (threadIdx.x < o) sh[threadIdx.x] += sh[threadIdx.x + o];
        __syncthreads();
    }
    if (threadIdx.x == 0) part[b * 64 + blockIdx.x] = sh[0];
}

__global__ void fin_sum_kernel(const float* __restrict__ part, float* __restrict__ binv)
{
    const int b = blockIdx.x;
    __shared__ float sh[64];
    sh[threadIdx.x] = part[b * 64 + threadIdx.x];
    __syncthreads();
    for (int o = 32; o > 0; o >>= 1) {
        if (threadIdx.x < o) sh[threadIdx.x] += sh[threadIdx.x + o];
        __syncthreads();
    }
    if (threadIdx.x == 0) binv[b] = 1.f / sh[0];
}

// ---------------- fused residual-add + LayerNorm ----------------
// out[row] = LN(a[row] + res[row]) * gamma + beta, row length EDIM=1024,
// one block of 256 threads per row (4 elements per thread).
__global__ __launch_bounds__(256)
void add_ln_kernel(const float* __restrict__ a, const float* __restrict__ res,
                   const float* __restrict__ gam, const float* __restrict__ bet,
                   float* __restrict__ out)
{
    const int row = blockIdx.x;
    const int t = threadIdx.x;
    const float4 va = ((const float4*)(a + (size_t)row * EDIM))[t];
    const float4 vr = ((const float4*)(res + (size_t)row * EDIM))[t];
    float x0 = va.x + vr.x, x1 = va.y + vr.y, x2 = va.z + vr.z, x3 = va.w + vr.w;

    __shared__ float sh[256];
    sh[t] = (x0 + x1) + (x2 + x3);
    __syncthreads();
    for (int o = 128; o > 0; o >>= 1) {
        if (t < o) sh[t] += sh[t + o];
        __syncthreads();
    }
    const float mean = sh[0] * (1.f / EDIM);
    __syncthreads();

    const float d0 = x0 - mean, d1 = x1 - mean, d2 = x2 - mean, d3 = x3 - mean;
    sh[t] = (d0 * d0 + d1 * d1) + (d2 * d2 + d3 * d3);
    __syncthreads();
    for (int o = 128; o > 0; o >>= 1) {
        if (t < o) sh[t] += sh[t + o];
        __syncthreads();
    }
    const float rstd = rsqrtf(sh[0] * (1.f / EDIM) + 1e-5f);

    const float4 vg = ((const float4*)gam)[t];
    const float4 vb = ((const float4*)bet)[t];
    float4 o4;
    o4.x = d0 * rstd * vg.x + vb.x;
    o4.y = d1 * rstd * vg.y + vb.y;
    o4.z = d2 * rstd * vg.z + vb.z;
    o4.w = d3 * rstd * vg.w + vb.w;
    ((float4*)(out + (size_t)row * EDIM))[t] = o4;
}

// ---------------- launch ----------------
extern "C" void kernel_launch(void* const* d_in, const int* in_sizes, int n_in,
                              void* d_out, int out_size)
{
    const float* pl   = (const float*)d_in[0];
    const float* sam  = (const float*)d_in[1];
    const float* Wq   = (const float*)d_in[2];
    const float* Wk   = (const float*)d_in[3];
    const float* Wv   = (const float*)d_in[4];
    const float* ln1g = (const float*)d_in[5];
    const float* ln1b = (const float*)d_in[6];
    const float* W1   = (const float*)d_in[7];
    const float* W2   = (const float*)d_in[8];
    const float* ln2g = (const float*)d_in[9];
    const float* ln2b = (const float*)d_in[10];
    float* out = (float*)d_out;

    float *q, *k, *v, *w, *x, *h, *part, *bmax, *binv;
    cudaGetSymbolAddress((void**)&q, g_q);
    cudaGetSymbolAddress((void**)&k, g_k);
    cudaGetSymbolAddress((void**)&v, g_v);
    cudaGetSymbolAddress((void**)&w, g_w);
    cudaGetSymbolAddress((void**)&x, g_x);
    cudaGetSymbolAddress((void**)&h, g_h);
    cudaGetSymbolAddress((void**)&part, g_part);
    cudaGetSymbolAddress((void**)&bmax, g_bmax);
    cudaGetSymbolAddress((void**)&binv, g_binv);

    const int MS = BSZ * SDIM;            // 16384
    const long long sSE = (long long)SDIM * EDIM;
    const long long sSS = (long long)SDIM * SDIM;

    // q = pl @ Wq ; k = sam @ Wk ; v = sam @ Wv
    gemm_kernel<false><<<dim3(EDIM / 128, MS / 128, 1), 256>>>(
        pl, Wq, q, MS, EDIM, EDIM, 0, 0, 0, 1.f, nullptr);
    gemm_kernel<false><<<dim3(EDIM / 128, MS / 128, 1), 256>>>(
        sam, Wk, k, MS, EDIM, EDIM, 0, 0, 0, 1.f, nullptr);
    gemm_kernel<false><<<dim3(EDIM / 128, MS / 128, 1), 256>>>(
        sam, Wv, v, MS, EDIM, EDIM, 0, 0, 0, 1.f, nullptr);

    // scores = (q @ k^T) / sqrt(E), per batch
    gemm_kernel<true><<<dim3(SDIM / 128, SDIM / 128, BSZ), 256>>>(
        q, k, w, SDIM, SDIM, EDIM, sSE, sSE, sSS, 0.03125f, nullptr);

    // flattened softmax per batch
    max_part_kernel<<<dim3(64, BSZ), 256>>>(w, part);
    fin_max_kernel<<<BSZ, 64>>>(part, bmax);
    expsum_kernel<<<dim3(64, BSZ), 256>>>(w, bmax, part);
    fin_sum_kernel<<<BSZ, 64>>>(part, binv);

    // attn = softmax(w) @ v  (normalization folded into per-batch alpha), into q
    gemm_kernel<false><<<dim3(EDIM / 128, SDIM / 128, BSZ), 256>>>(
        w, v, q, SDIM, EDIM, SDIM, sSS, sSE, sSE, 1.f, binv);

    // x = LN(attn + pl)
    add_ln_kernel<<<MS, 256>>>(q, pl, ln1g, ln1b, x);

    // h = x @ W1 ; ff = h @ W2 (into k buffer)
    gemm_kernel<false><<<dim3(HDIM / 128, MS / 128, 1), 256>>>(
        x, W1, h, MS, HDIM, EDIM, 0, 0, 0, 1.f, nullptr);
    gemm_kernel<false><<<dim3(EDIM / 128, MS / 128, 1), 256>>>(
        h, W2, k, MS, EDIM, HDIM, 0, 0, 0, 1.f, nullptr);

    // out = LN(ff + x)
    add_ln_kernel<<<MS, 256>>>(k, x, ln2g, ln2b, out);
}

// round 3
// speedup vs baseline: 3.2557x; 3.2557x over previous
#include <cuda_runtime.h>
#include <cstdint>

#define BSZ 16
#define SDIM 1024
#define EDIM 1024
#define HDIM 2048
#define MSALL (BSZ * SDIM)

// ---------------- scratch (device globals; no allocations) ----------------
__device__ float g_plr[(size_t)MSALL * EDIM];   // rounded pl
__device__ float g_samr[(size_t)MSALL * EDIM];  // rounded sam, later x_r
__device__ float g_q[(size_t)MSALL * EDIM];     // q (rounded), later attn (fp32)
__device__ float g_k[(size_t)MSALL * EDIM];     // k (rounded), later x (fp32)
__device__ float g_v[(size_t)MSALL * EDIM];     // v (fp32), later ff (fp32)
__device__ float g_vT[(size_t)MSALL * EDIM];    // v^T per batch (rounded)
__device__ float g_w[(size_t)BSZ * SDIM * SDIM];// scores -> rounded softmax weights
__device__ float g_h[(size_t)MSALL * HDIM];     // FFN hidden (rounded)
__device__ float g_WqT[EDIM * EDIM];
__device__ float g_WkT[EDIM * EDIM];
__device__ float g_WvT[EDIM * EDIM];
__device__ float g_W1T[EDIM * HDIM];
__device__ float g_W2T[EDIM * HDIM];
__device__ float g_part[BSZ * 64];
__device__ float g_bmax[BSZ];
__device__ float g_binv[BSZ];

__device__ __forceinline__ float rna(float v) {
    uint32_t u;
    asm("cvt.rna.tf32.f32 %0, %1;" : "=r"(u) : "f"(v));
    return __uint_as_float(u);
}

// ---------------- warp-MMA tf32 GEMM (mma.sync, sm80-style multistage) ----
// C[M,N] = alpha * A[M,K] @ B[N,K]^T. A,B fp32 (tf32-rounded), K-major.
// CTA 128x128, BK=16, 4 stages, 128 threads, 4 warps (2x2) of 64x64.
#define BMDIM 128
#define BKDIM 16
#define NSTAGE 4
#define APAD_STRIDE 20                         // floats per row (16 + 4 pad)
#define TILE_BYTES (BMDIM * APAD_STRIDE * 4)   // 10240
#define STAGE_BYTES (2 * TILE_BYTES)           // 20480
#define GEMM_SMEM (NSTAGE * STAGE_BYTES)       // 81920

__device__ __forceinline__ void cp_async16(uint32_t dst, const float* src) {
    size_t ga = __cvta_generic_to_global(src);
    asm volatile("cp.async.cg.shared.global [%0], [%1], 16;"
                 :: "r"(dst), "l"(ga) : "memory");
}

__device__ __forceinline__ void mma_tf32(float* c, const uint32_t* a, const uint32_t* b) {
    asm volatile(
        "mma.sync.aligned.m16n8k8.row.col.f32.tf32.tf32.f32 "
        "{%0,%1,%2,%3}, {%4,%5,%6,%7}, {%8,%9}, {%0,%1,%2,%3};"
        : "+f"(c[0]), "+f"(c[1]), "+f"(c[2]), "+f"(c[3])
        : "r"(a[0]), "r"(a[1]), "r"(a[2]), "r"(a[3]), "r"(b[0]), "r"(b[1]));
}

__device__ __forceinline__ uint32_t s2u(const void* p) {
    uint32_t a;
    asm("{ .reg .u64 t; cvta.to.shared.u64 t, %1; cvt.u32.u64 %0, t; }"
        : "=r"(a) : "l"(p));
    return a;
}

template <bool ROUND>
__global__ __launch_bounds__(128, 2)
void gemm_tc(const float* __restrict__ A, const float* __restrict__ B,
             float* __restrict__ C, int N, int K,
             long long sA, long long sB, long long sC,
             float alpha, const float* __restrict__ alphaPtr)
{
    extern __shared__ char smem[];
    const uint32_t sb = s2u(smem);
    const int tid = threadIdx.x;
    const int bz = blockIdx.z;
    A += (long long)bz * sA;
    B += (long long)bz * sB;
    C += (long long)bz * sC;
    const int m0 = blockIdx.y * BMDIM;
    const int n0 = blockIdx.x * BMDIM;
    const int nk = K / BKDIM;

    const int warp = tid >> 5, lane = tid & 31;
    const int wm = (warp & 1) * 64;   // warp m offset
    const int wn = (warp >> 1) * 64;  // warp n offset
    const int lg = lane >> 2;         // group id (0-7)
    const int lt = lane & 3;          // thread in group

    // per-thread load slots: 8 chunks of 16B per stage (A:4, B:4)
    // chunk idx = tid + i*128 -> row = idx/4, ch = idx%4
    const int lrow = tid >> 2;
    const int lch = tid & 3;

    float acc[4][8][4];
#pragma unroll
    for (int i = 0; i < 4; i++)
#pragma unroll
        for (int j = 0; j < 8; j++)
#pragma unroll
            for (int c = 0; c < 4; c++) acc[i][j][c] = 0.f;

    // -------- prologue: fill stages 0..NSTAGE-2 --------
#pragma unroll
    for (int j = 0; j < NSTAGE - 1; j++) {
        uint32_t st = sb + j * STAGE_BYTES;
        int kt = j * BKDIM;
#pragma unroll
        for (int i = 0; i < 4; i++) {
            int row = lrow + i * 32;
            cp_async16(st + row * (APAD_STRIDE * 4) + lch * 16,
                       A + (long long)(m0 + row) * K + kt + lch * 4);
            cp_async16(st + TILE_BYTES + row * (APAD_STRIDE * 4) + lch * 16,
                       B + (long long)(n0 + row) * K + kt + lch * 4);
        }
        asm volatile("cp.async.commit_group;" ::: "memory");
    }

    for (int i = 0; i < nk; i++) {
        const int s = i % NSTAGE;
        const int rem = nk - 1 - i;
        if (rem >= 2)
            asm volatile("cp.async.wait_group 2;" ::: "memory");
        else if (rem == 1)
            asm volatile("cp.async.wait_group 1;" ::: "memory");
        else
            asm volatile("cp.async.wait_group 0;" ::: "memory");
        __syncthreads();

        // prefetch stage i+NSTAGE-1 into slot (i-1)%NSTAGE
        int jn = i + NSTAGE - 1;
        if (jn < nk) {
            uint32_t st = sb + (jn % NSTAGE) * STAGE_BYTES;
            int kt = jn * BKDIM;
#pragma unroll
            for (int u = 0; u < 4; u++) {
                int row = lrow + u * 32;
                cp_async16(st + row * (APAD_STRIDE * 4) + lch * 16,
                           A + (long long)(m0 + row) * K + kt + lch * 4);
                cp_async16(st + TILE_BYTES + row * (APAD_STRIDE * 4) + lch * 16,
                           B + (long long)(n0 + row) * K + kt + lch * 4);
            }
            asm volatile("cp.async.commit_group;" ::: "memory");
        }

        // -------- compute stage s: 2 k8-steps --------
        const float* As = (const float*)(smem + s * STAGE_BYTES);
        const float* Bs = (const float*)(smem + s * STAGE_BYTES + TILE_BYTES);
        const float* ap0 = As + (wm + lg) * APAD_STRIDE + lt;
        const float* bp0 = Bs + (wn + lg) * APAD_STRIDE + lt;
#pragma unroll
        for (int ks = 0; ks < 2; ks++) {
            const float* ap = ap0 + ks * 8;
            const float* bp = bp0 + ks * 8;
            uint32_t af[4][4], bf[8][2];
#pragma unroll
            for (int mf = 0; mf < 4; mf++) {
                const float* p = ap + mf * (16 * APAD_STRIDE);
                af[mf][0] = __float_as_uint(p[0]);
                af[mf][1] = __float_as_uint(p[8 * APAD_STRIDE]);
                af[mf][2] = __float_as_uint(p[4]);
                af[mf][3] = __float_as_uint(p[8 * APAD_STRIDE + 4]);
            }
#pragma unroll
            for (int nf = 0; nf < 8; nf++) {
                const float* p = bp + nf * (8 * APAD_STRIDE);
                bf[nf][0] = __float_as_uint(p[0]);
                bf[nf][1] = __float_as_uint(p[4]);
            }
#pragma unroll
            for (int mf = 0; mf < 4; mf++)
#pragma unroll
                for (int nf = 0; nf < 8; nf++)
                    mma_tf32(acc[mf][nf], af[mf], bf[nf]);
        }
        __syncthreads();
    }

    // -------- epilogue --------
    const float aeff = alpha * (alphaPtr ? alphaPtr[bz] : 1.f);
#pragma unroll
    for (int mf = 0; mf < 4; mf++) {
        int r0 = m0 + wm + mf * 16 + lg;
#pragma unroll
        for (int nf = 0; nf < 8; nf++) {
            int cc = n0 + wn + nf * 8 + 2 * lt;
            float2 v0, v1;
            v0.x = acc[mf][nf][0] * aeff;
            v0.y = acc[mf][nf][1] * aeff;
            v1.x = acc[mf][nf][2] * aeff;
            v1.y = acc[mf][nf][3] * aeff;
            if (ROUND) {
                v0.x = rna(v0.x); v0.y = rna(v0.y);
                v1.x = rna(v1.x); v1.y = rna(v1.y);
            }
            *(float2*)&C[(long long)r0 * N + cc] = v0;
            *(float2*)&C[(long long)(r0 + 8) * N + cc] = v1;
        }
    }
}

// ---------------- elementwise round-copy ----------------
__global__ __launch_bounds__(256)
void round_copy_kernel(const float* __restrict__ s, float* __restrict__ d, int n4)
{
    int i = blockIdx.x * 256 + threadIdx.x;
    if (i < n4) {
        float4 v = ((const float4*)s)[i];
        v.x = rna(v.x); v.y = rna(v.y); v.z = rna(v.z); v.w = rna(v.w);
        ((float4*)d)[i] = v;
    }
}

// ---------------- transpose + round ----------------
__global__ void transpose_round_kernel(const float* __restrict__ src,
                                       float* __restrict__ dst,
                                       int rows, int cols,
                                       long long sS, long long sD)
{
    __shared__ float tile[32][33];
    src += (long long)blockIdx.z * sS;
    dst += (long long)blockIdx.z * sD;
    int c0 = blockIdx.x * 32, r0 = blockIdx.y * 32;
    int x = threadIdx.x, y = threadIdx.y;
#pragma unroll
    for (int i = 0; i < 32; i += 8)
        tile[y + i][x] = src[(long long)(r0 + y + i) * cols + c0 + x];
    __syncthreads();
#pragma unroll
    for (int i = 0; i < 32; i += 8)
        dst[(long long)(c0 + y + i) * rows + r0 + x] = rna(tile[x][y + i]);
}

// ---------------- softmax over flattened S*S per batch ----------------
__global__ __launch_bounds__(256)
void max_part_kernel(const float* __restrict__ w, float* __restrict__ part)
{
    const int b = blockIdx.y;
    const float4* p = (const float4*)(w + (size_t)b * SDIM * SDIM)
                      + (size_t)blockIdx.x * 4096;
    float m = -3.4e38f;
    for (int i = threadIdx.x; i < 4096; i += 256) {
        float4 v = p[i];
        m = fmaxf(m, fmaxf(fmaxf(v.x, v.y), fmaxf(v.z, v.w)));
    }
    __shared__ float sh[256];
    sh[threadIdx.x] = m;
    __syncthreads();
    for (int o = 128; o > 0; o >>= 1) {
        if (threadIdx.x < o)
            sh[threadIdx.x] = fmaxf(sh[threadIdx.x], sh[threadIdx.x + o]);
        __syncthreads();
    }
    if (threadIdx.x == 0) part[b * 64 + blockIdx.x] = sh[0];
}

__global__ void fin_max_kernel(const float* __restrict__ part, float* __restrict__ bmax)
{
    const int b = blockIdx.x;
    __shared__ float sh[64];
    sh[threadIdx.x] = part[b * 64 + threadIdx.x];
    __syncthreads();
    for (int o = 32; o > 0; o >>= 1) {
        if (threadIdx.x < o)
            sh[threadIdx.x] = fmaxf(sh[threadIdx.x], sh[threadIdx.x + o]);
        __syncthreads();
    }
    if (threadIdx.x == 0) bmax[b] = sh[0];
}

__global__ __launch_bounds__(256)
void expsum_kernel(float* __restrict__ w, const float* __restrict__ bmax,
                   float* __restrict__ part)
{
    const int b = blockIdx.y;
    const float m = bmax[b];
    float4* p = (float4*)(w + (size_t)b * SDIM * SDIM) + (size_t)blockIdx.x * 4096;
    float s = 0.f;
    for (int i = threadIdx.x; i < 4096; i += 256) {
        float4 v = p[i];
        v.x = rna(__expf(v.x - m));
        v.y = rna(__expf(v.y - m));
        v.z = rna(__expf(v.z - m));
        v.w = rna(__expf(v.w - m));
        s += (v.x + v.y) + (v.z + v.w);
        p[i] = v;
    }
    __shared__ float sh[256];
    sh[threadIdx.x] = s;
    __syncthreads();
    for (int o = 128; o > 0; o >>= 1) {
        if (threadIdx.x < o) sh[threadIdx.x] += sh[threadIdx.x + o];
        __syncthreads();
    }
    if (threadIdx.x == 0) part[b * 64 + blockIdx.x] = sh[0];
}

__global__ void fin_sum_kernel(const float* __restrict__ part, float* __restrict__ binv)
{
    const int b = blockIdx.x;
    __shared__ float sh[64];
    sh[threadIdx.x] = part[b * 64 + threadIdx.x];
    __syncthreads();
    for (int o = 32; o > 0; o >>= 1) {
        if (threadIdx.x < o) sh[threadIdx.x] += sh[threadIdx.x + o];
        __syncthreads();
    }
    if (threadIdx.x == 0) binv[b] = 1.f / sh[0];
}

// ---------------- fused residual-add + LayerNorm (+optional tf32 copy) ----
__global__ __launch_bounds__(256)
void add_ln_kernel(const float* __restrict__ a, const float* __restrict__ res,
                   const float* __restrict__ gam, const float* __restrict__ bet,
                   float* __restrict__ out, float* __restrict__ out_r)
{
    const int row = blockIdx.x;
    const int t = threadIdx.x;
    const float4 va = ((const float4*)(a + (size_t)row * EDIM))[t];
    const float4 vr = ((const float4*)(res + (size_t)row * EDIM))[t];
    float x0 = va.x + vr.x, x1 = va.y + vr.y, x2 = va.z + vr.z, x3 = va.w + vr.w;

    __shared__ float sh[256];
    sh[t] = (x0 + x1) + (x2 + x3);
    __syncthreads();
    for (int o = 128; o > 0; o >>= 1) {
        if (t < o) sh[t] += sh[t + o];
        __syncthreads();
    }
    const float mean = sh[0] * (1.f / EDIM);
    __syncthreads();

    const float d0 = x0 - mean, d1 = x1 - mean, d2 = x2 - mean, d3 = x3 - mean;
    sh[t] = (d0 * d0 + d1 * d1) + (d2 * d2 + d3 * d3);
    __syncthreads();
    for (int o = 128; o > 0; o >>= 1) {
        if (t < o) sh[t] += sh[t + o];
        __syncthreads();
    }
    const float rstd = rsqrtf(sh[0] * (1.f / EDIM) + 1e-5f);

    const float4 vg = ((const float4*)gam)[t];
    const float4 vb = ((const float4*)bet)[t];
    float4 o4;
    o4.x = d0 * rstd * vg.x + vb.x;
    o4.y = d1 * rstd * vg.y + vb.y;
    o4.z = d2 * rstd * vg.z + vb.z;
    o4.w = d3 * rstd * vg.w + vb.w;
    ((float4*)(out + (size_t)row * EDIM))[t] = o4;
    if (out_r) {
        float4 r4;
        r4.x = rna(o4.x); r4.y = rna(o4.y); r4.z = rna(o4.z); r4.w = rna(o4.w);
        ((float4*)(out_r + (size_t)row * EDIM))[t] = r4;
    }
}

// ---------------- launch ----------------
extern "C" void kernel_launch(void* const* d_in, const int* in_sizes, int n_in,
                              void* d_out, int out_size)
{
    const float* pl   = (const float*)d_in[0];
    const float* sam  = (const float*)d_in[1];
    const float* Wq   = (const float*)d_in[2];
    const float* Wk   = (const float*)d_in[3];
    const float* Wv   = (const float*)d_in[4];
    const float* ln1g = (const float*)d_in[5];
    const float* ln1b = (const float*)d_in[6];
    const float* W1   = (const float*)d_in[7];
    const float* W2   = (const float*)d_in[8];
    const float* ln2g = (const float*)d_in[9];
    const float* ln2b = (const float*)d_in[10];
    float* out = (float*)d_out;

    float *plr, *samr, *q, *k, *v, *vT, *w, *h;
    float *WqT, *WkT, *WvT, *W1T, *W2T, *part, *bmax, *binv;
    cudaGetSymbolAddress((void**)&plr, g_plr);
    cudaGetSymbolAddress((void**)&samr, g_samr);
    cudaGetSymbolAddress((void**)&q, g_q);
    cudaGetSymbolAddress((void**)&k, g_k);
    cudaGetSymbolAddress((void**)&v, g_v);
    cudaGetSymbolAddress((void**)&vT, g_vT);
    cudaGetSymbolAddress((void**)&w, g_w);
    cudaGetSymbolAddress((void**)&h, g_h);
    cudaGetSymbolAddress((void**)&WqT, g_WqT);
    cudaGetSymbolAddress((void**)&WkT, g_WkT);
    cudaGetSymbolAddress((void**)&WvT, g_WvT);
    cudaGetSymbolAddress((void**)&W1T, g_W1T);
    cudaGetSymbolAddress((void**)&W2T, g_W2T);
    cudaGetSymbolAddress((void**)&part, g_part);
    cudaGetSymbolAddress((void**)&bmax, g_bmax);
    cudaGetSymbolAddress((void**)&binv, g_binv);

    cudaFuncSetAttribute(gemm_tc<false>, cudaFuncAttributeMaxDynamicSharedMemorySize, GEMM_SMEM);
    cudaFuncSetAttribute(gemm_tc<true>,  cudaFuncAttributeMaxDynamicSharedMemorySize, GEMM_SMEM);

    const long long sSE = (long long)SDIM * EDIM;
    const long long sSS = (long long)SDIM * SDIM;

    // round inputs to tf32
    round_copy_kernel<<<(MSALL * EDIM / 4 + 255) / 256, 256>>>(pl, plr, MSALL * EDIM / 4);
    round_copy_kernel<<<(MSALL * EDIM / 4 + 255) / 256, 256>>>(sam, samr, MSALL * EDIM / 4);

    // transpose + round weights: W^T is [N,K] K-major
    transpose_round_kernel<<<dim3(32, 32, 1), dim3(32, 8)>>>(Wq, WqT, EDIM, EDIM, 0, 0);
    transpose_round_kernel<<<dim3(32, 32, 1), dim3(32, 8)>>>(Wk, WkT, EDIM, EDIM, 0, 0);
    transpose_round_kernel<<<dim3(32, 32, 1), dim3(32, 8)>>>(Wv, WvT, EDIM, EDIM, 0, 0);
    transpose_round_kernel<<<dim3(64, 32, 1), dim3(32, 8)>>>(W1, W1T, EDIM, HDIM, 0, 0);
    transpose_round_kernel<<<dim3(32, 64, 1), dim3(32, 8)>>>(W2, W2T, HDIM, EDIM, 0, 0);

    // q = pl @ Wq (rounded), k = sam @ Wk (rounded), v = sam @ Wv (fp32)
    gemm_tc<true><<<dim3(EDIM / 128, MSALL / 128, 1), 128, GEMM_SMEM>>>(
        plr, WqT, q, EDIM, EDIM, 0, 0, 0, 1.f, nullptr);
    gemm_tc<true><<<dim3(EDIM / 128, MSALL / 128, 1), 128, GEMM_SMEM>>>(
        samr, WkT, k, EDIM, EDIM, 0, 0, 0, 1.f, nullptr);
    gemm_tc<false><<<dim3(EDIM / 128, MSALL / 128, 1), 128, GEMM_SMEM>>>(
        samr, WvT, v, EDIM, EDIM, 0, 0, 0, 1.f, nullptr);

    // vT per batch (rounded)
    transpose_round_kernel<<<dim3(32, 32, BSZ), dim3(32, 8)>>>(
        v, vT, SDIM, EDIM, sSE, sSE);

    // scores = (q @ k^T) / 32 per batch
    gemm_tc<false><<<dim3(SDIM / 128, SDIM / 128, BSZ), 128, GEMM_SMEM>>>(
        q, k, w, SDIM, EDIM, sSE, sSE, sSS, 0.03125f, nullptr);

    // flattened softmax per batch (stores tf32-rounded weights)
    max_part_kernel<<<dim3(64, BSZ), 256>>>(w, part);
    fin_max_kernel<<<BSZ, 64>>>(part, bmax);
    expsum_kernel<<<dim3(64, BSZ), 256>>>(w, bmax, part);
    fin_sum_kernel<<<BSZ, 64>>>(part, binv);

    // attn = (w @ vT^T) * binv  -> into q (fp32)
    gemm_tc<false><<<dim3(EDIM / 128, SDIM / 128, BSZ), 128, GEMM_SMEM>>>(
        w, vT, q, EDIM, SDIM, sSS, sSE, sSE, 1.f, binv);

    // x = LN(attn + pl): fp32 into k, rounded into samr
    add_ln_kernel<<<MSALL, 256>>>(q, pl, ln1g, ln1b, k, samr);

    // h = x @ W1 (rounded); ff = h @ W2 (fp32 into v)
    gemm_tc<true><<<dim3(HDIM / 128, MSALL / 128, 1), 128, GEMM_SMEM>>>(
        samr, W1T, h, HDIM, EDIM, 0, 0, 0, 1.f, nullptr);
    gemm_tc<false><<<dim3(EDIM / 128, MSALL / 128, 1), 128, GEMM_SMEM>>>(
        h, W2T, v, EDIM, HDIM, 0, 0, 0, 1.f, nullptr);

    // out = LN(ff + x)
    add_ln_kernel<<<MSALL, 256>>>(v, k, ln2g, ln2b, out, nullptr);
}